// round 10
// baseline (speedup 1.0000x reference)
#include <cuda_runtime.h>
#include <math.h>

// MonotonicSpline: y[i] = cubic uniform B-spline(clip(x[i],0,1)).
// coef[0]=c0; coef[j]=c0 + sum_{i<j}(MIN+(MAX-MIN)*sigmoid(raw_delta[i])).
// Uniform knots h=1/40 -> per-segment cubic y = ((a*u+b)*u+c)*u+d, u=frac(40x).
//
// BARRIER-FREE fused prologue: every warp redundantly computes the identical
// coef scan and writes the identical 8-way-replicated poly table (racy but
// same-value word stores -> deterministic). No __syncthreads anywhere: warps
// issue their 4 data LDG.128 first, run the ~170-instr prologue under those
// loads' latency, then consume and retire independently (R9 showed the
// block-wide barrier convoy costs ~1us vs the barrier-free R2 eval).
// ITEMS=4 contiguous chunks, 1024 exact blocks, launch_bounds(256,8)
// (regs<=32, one resident wave). Zero-conflict lane8 LDS.128 gathers.

static constexpr int   NUM_KNOTS = 40;
static constexpr float MIN_DELTA = 0.5f / NUM_KNOTS;
static constexpr float MAX_DELTA = 3.0f / NUM_KNOTS;
static constexpr int   THREADS   = 256;
static constexpr int   ITEMS     = 4;

__device__ __forceinline__ float eval_one(float xv, const float4* __restrict__ rep,
                                          int lane8) {
    float t   = __saturatef(xv) * (float)NUM_KNOTS;   // t in [0,40]
    int   idx = min(__float2int_rz(t), NUM_KNOTS - 1);
    float u   = t - (float)idx;                        // u in [0,1]
    float4 p  = rep[idx * 8 + lane8];                  // conflict-free LDS.128
    return ((p.w * u + p.z) * u + p.y) * u + p.x;
}

__global__ void __launch_bounds__(THREADS, 8)
spline_fused_kernel(const float* __restrict__ x,
                    const float* __restrict__ c0,
                    const float* __restrict__ raw_delta,
                    float* __restrict__ y,
                    int n4, int n) {
    __shared__ float  coef[NUM_KNOTS + 3];      // 43 (racy-identical writes)
    __shared__ float4 rep[NUM_KNOTS * 8];       // 5 KB (racy-identical writes)

    const int tid  = threadIdx.x;
    const int lane = tid & 31;
    const int base = blockIdx.x * (THREADS * ITEMS) + tid;
    const bool full = (blockIdx.x + 1) * (THREADS * ITEMS) <= n4;
    const float4* __restrict__ x4 = reinterpret_cast<const float4*>(x);
    float4* __restrict__ y4 = reinterpret_cast<float4*>(y);

    // ---- issue data loads FIRST; prologue runs under their latency ----
    float4 v0, v1, v2, v3;
    if (full) {
        v0 = x4[base + 0 * THREADS];
        v1 = x4[base + 1 * THREADS];
        v2 = x4[base + 2 * THREADS];
        v3 = x4[base + 3 * THREADS];
    } else {
        if (base + 0 * THREADS < n4) v0 = x4[base + 0 * THREADS];
        if (base + 1 * THREADS < n4) v1 = x4[base + 1 * THREADS];
        if (base + 2 * THREADS < n4) v2 = x4[base + 2 * THREADS];
        if (base + 3 * THREADS < n4) v3 = x4[base + 3 * THREADS];
    }

    // ---- EVERY warp: sigmoid deltas -> shfl scan -> coef -> poly table ----
    // All warps compute and store identical values; no cross-warp sync needed.
    {
        const float scale = MAX_DELTA - MIN_DELTA;
        float d0 = MIN_DELTA + scale / (1.0f + __expf(-__ldg(raw_delta + lane)));
        float d1 = 0.0f;
        if (lane < 10)
            d1 = MIN_DELTA + scale / (1.0f + __expf(-__ldg(raw_delta + lane + 32)));
        #pragma unroll
        for (int off = 1; off < 32; off <<= 1) {
            float t0 = __shfl_up_sync(0xffffffffu, d0, off);
            float t1 = __shfl_up_sync(0xffffffffu, d1, off);
            if (lane >= off) { d0 += t0; d1 += t1; }
        }
        float tot0 = __shfl_sync(0xffffffffu, d0, 31);
        float c0v  = __ldg(c0);
        if (lane == 0) coef[0] = c0v;
        coef[lane + 1] = c0v + d0;                        // coef[1..32]
        if (lane < 10) coef[lane + 33] = c0v + tot0 + d1; // coef[33..42]
        __syncwarp();                                     // own writes visible
        #pragma unroll
        for (int e = lane; e < NUM_KNOTS * 8; e += 32) {  // conflict-free STS.128
            int j = e >> 3;
            float p0 = coef[j], p1 = coef[j + 1], p2 = coef[j + 2], p3 = coef[j + 3];
            float4 o;
            o.x = (p0 + 4.0f * p1 + p2) * (1.0f / 6.0f);
            o.y = (p2 - p0) * 0.5f;
            o.z = (p0 - 2.0f * p1 + p2) * 0.5f;
            o.w = (p3 - p0 + 3.0f * (p1 - p2)) * (1.0f / 6.0f);
            rep[e] = o;
        }
        __syncwarp();                                     // table visible to warp
    }

    // ---- gather + Horner + store (immediate-offset STG.128) ----
    const int lane8 = tid & 7;
    if (full) {
        float4 o;
        o.x = eval_one(v0.x, rep, lane8); o.y = eval_one(v0.y, rep, lane8);
        o.z = eval_one(v0.z, rep, lane8); o.w = eval_one(v0.w, rep, lane8);
        y4[base + 0 * THREADS] = o;
        o.x = eval_one(v1.x, rep, lane8); o.y = eval_one(v1.y, rep, lane8);
        o.z = eval_one(v1.z, rep, lane8); o.w = eval_one(v1.w, rep, lane8);
        y4[base + 1 * THREADS] = o;
        o.x = eval_one(v2.x, rep, lane8); o.y = eval_one(v2.y, rep, lane8);
        o.z = eval_one(v2.z, rep, lane8); o.w = eval_one(v2.w, rep, lane8);
        y4[base + 2 * THREADS] = o;
        o.x = eval_one(v3.x, rep, lane8); o.y = eval_one(v3.y, rep, lane8);
        o.z = eval_one(v3.z, rep, lane8); o.w = eval_one(v3.w, rep, lane8);
        y4[base + 3 * THREADS] = o;
    } else {
        float4 vv[4] = {v0, v1, v2, v3};
        #pragma unroll
        for (int it = 0; it < ITEMS; ++it) {
            int i = base + it * THREADS;
            if (i < n4) {
                float4 o;
                o.x = eval_one(vv[it].x, rep, lane8);
                o.y = eval_one(vv[it].y, rep, lane8);
                o.z = eval_one(vv[it].z, rep, lane8);
                o.w = eval_one(vv[it].w, rep, lane8);
                y4[i] = o;
            }
        }
    }

    // scalar tail (n % 4 != 0) — block 0 only
    if (blockIdx.x == 0) {
        int j = n4 * 4 + tid;
        if (j < n) y[j] = eval_one(x[j], rep, lane8);
    }
}

extern "C" void kernel_launch(void* const* d_in, const int* in_sizes, int n_in,
                              void* d_out, int out_size) {
    const float* x         = (const float*)d_in[0];
    // d_in[1] = grid (uniform; values implied by construction)
    const float* c0        = (const float*)d_in[2];
    const float* raw_delta = (const float*)d_in[3];
    float* y = (float*)d_out;

    int n  = in_sizes[0];
    int n4 = n / 4;

    int per_block = THREADS * ITEMS;
    int blocks = (n4 + per_block - 1) / per_block;
    if (blocks == 0) blocks = 1;

    spline_fused_kernel<<<blocks, THREADS>>>(x, c0, raw_delta, y, n4, n);
}

// round 11
// speedup vs baseline: 1.1889x; 1.1889x over previous
#include <cuda_runtime.h>
#include <math.h>

// MonotonicSpline: y[i] = cubic uniform B-spline(clip(x[i],0,1)).
// coef[0]=c0; coef[j]=c0 + sum_{i<j}(MIN+(MAX-MIN)*sigmoid(raw_delta[i])).
// Uniform knots h=1/40 -> per-segment cubic y=((a*u+b)*u+c)*u+d, u=frac(40x).
//
// TWO kernels overlapped with PDL (programmatic dependent launch):
//  - prep (1 block / 32 thr): sigmoid -> shfl scan -> poly coeffs -> g_poly,
//    __threadfence + cudaTriggerProgrammaticLaunchCompletion right after.
//  - eval: the R2 structure that measured 8.99us (ITEMS=4 contiguous chunks,
//    1024 blocks, regs<=32, 8-way replicated smem table, one barrier).
//    Its 4 x LDG.128 (independent of prep) issue BEFORE
//    cudaGridDependencySynchronize(), hiding prep's latency.
// Evidence: fused-prologue variants all plateau 10.0-10.5us (sigmoid+scan in
// every block costs ~1us however scheduled: R4/R5/R9/R10); R2 eval alone is
// 8.99us; graph node overhead is only ~0.2us (R9) — the 2us R2 paid was the
// serial prep node, which PDL overlaps.

static constexpr int   NUM_KNOTS = 40;
static constexpr float MIN_DELTA = 0.5f / NUM_KNOTS;
static constexpr float MAX_DELTA = 3.0f / NUM_KNOTS;
static constexpr int   THREADS   = 256;
static constexpr int   ITEMS     = 4;

__device__ float4 g_poly[NUM_KNOTS];   // per-segment (d,c,b,a)

// ---------------- prep: 1 block, 32 threads ----------------
__global__ void prep_kernel(const float* __restrict__ c0,
                            const float* __restrict__ raw_delta) {
    __shared__ float coef[NUM_KNOTS + 3];   // 43
    const int lane = threadIdx.x;           // 0..31

    const float scale = MAX_DELTA - MIN_DELTA;
    float d0 = MIN_DELTA + scale / (1.0f + __expf(-raw_delta[lane]));
    float d1 = 0.0f;
    if (lane < 10)
        d1 = MIN_DELTA + scale / (1.0f + __expf(-raw_delta[lane + 32]));
    #pragma unroll
    for (int off = 1; off < 32; off <<= 1) {
        float t0 = __shfl_up_sync(0xffffffffu, d0, off);
        float t1 = __shfl_up_sync(0xffffffffu, d1, off);
        if (lane >= off) { d0 += t0; d1 += t1; }
    }
    float tot0 = __shfl_sync(0xffffffffu, d0, 31);
    float c0v  = __ldg(c0);
    if (lane == 0) coef[0] = c0v;
    coef[lane + 1] = c0v + d0;                        // coef[1..32]
    if (lane < 10) coef[lane + 33] = c0v + tot0 + d1; // coef[33..42]
    __syncwarp();

    #pragma unroll
    for (int j = lane; j < NUM_KNOTS; j += 32) {
        float p0 = coef[j], p1 = coef[j + 1], p2 = coef[j + 2], p3 = coef[j + 3];
        float4 o;
        o.x = (p0 + 4.0f * p1 + p2) * (1.0f / 6.0f);      // u^0
        o.y = (p2 - p0) * 0.5f;                           // u^1
        o.z = (p0 - 2.0f * p1 + p2) * 0.5f;               // u^2
        o.w = (p3 - p0 + 3.0f * (p1 - p2)) * (1.0f / 6.0f); // u^3
        g_poly[j] = o;
    }
    __threadfence();
    cudaTriggerProgrammaticLaunchCompletion();   // let eval's gridsync return
}

// ---------------- eval: R2 structure + PDL gridsync ----------------
__device__ __forceinline__ float eval_one(float xv, const float4* __restrict__ rep,
                                          int lane8) {
    float t   = __saturatef(xv) * (float)NUM_KNOTS;   // t in [0,40]
    int   idx = min(__float2int_rz(t), NUM_KNOTS - 1);
    float u   = t - (float)idx;                        // u in [0,1]
    float4 p  = rep[idx * 8 + lane8];                  // conflict-free LDS.128
    return ((p.w * u + p.z) * u + p.y) * u + p.x;
}

__global__ void __launch_bounds__(THREADS, 8)
spline_eval_kernel(const float* __restrict__ x,
                   float* __restrict__ y,
                   int n4, int n) {
    __shared__ float4 rep[NUM_KNOTS * 8];   // 8-way replicated table, 5 KB

    const int tid  = threadIdx.x;
    const int base = blockIdx.x * (THREADS * ITEMS) + tid;
    const bool full = (blockIdx.x + 1) * (THREADS * ITEMS) <= n4;
    const float4* __restrict__ x4 = reinterpret_cast<const float4*>(x);
    float4* __restrict__ y4 = reinterpret_cast<float4*>(y);

    // ---- x loads are independent of prep: issue BEFORE gridsync ----
    float4 v0, v1, v2, v3;
    if (full) {
        v0 = x4[base + 0 * THREADS];
        v1 = x4[base + 1 * THREADS];
        v2 = x4[base + 2 * THREADS];
        v3 = x4[base + 3 * THREADS];
    } else {
        if (base + 0 * THREADS < n4) v0 = x4[base + 0 * THREADS];
        if (base + 1 * THREADS < n4) v1 = x4[base + 1 * THREADS];
        if (base + 2 * THREADS < n4) v2 = x4[base + 2 * THREADS];
        if (base + 3 * THREADS < n4) v3 = x4[base + 3 * THREADS];
    }

    // ---- wait for prep's g_poly writes, then cheap table copy ----
    cudaGridDependencySynchronize();
    #pragma unroll
    for (int e = tid; e < NUM_KNOTS * 8; e += THREADS)
        rep[e] = g_poly[e >> 3];
    __syncthreads();

    // ---- gather + Horner + store (immediate-offset STG.128) ----
    const int lane8 = tid & 7;
    if (full) {
        float4 o;
        o.x = eval_one(v0.x, rep, lane8); o.y = eval_one(v0.y, rep, lane8);
        o.z = eval_one(v0.z, rep, lane8); o.w = eval_one(v0.w, rep, lane8);
        y4[base + 0 * THREADS] = o;
        o.x = eval_one(v1.x, rep, lane8); o.y = eval_one(v1.y, rep, lane8);
        o.z = eval_one(v1.z, rep, lane8); o.w = eval_one(v1.w, rep, lane8);
        y4[base + 1 * THREADS] = o;
        o.x = eval_one(v2.x, rep, lane8); o.y = eval_one(v2.y, rep, lane8);
        o.z = eval_one(v2.z, rep, lane8); o.w = eval_one(v2.w, rep, lane8);
        y4[base + 2 * THREADS] = o;
        o.x = eval_one(v3.x, rep, lane8); o.y = eval_one(v3.y, rep, lane8);
        o.z = eval_one(v3.z, rep, lane8); o.w = eval_one(v3.w, rep, lane8);
        y4[base + 3 * THREADS] = o;
    } else {
        float4 vv[4] = {v0, v1, v2, v3};
        #pragma unroll
        for (int it = 0; it < ITEMS; ++it) {
            int i = base + it * THREADS;
            if (i < n4) {
                float4 o;
                o.x = eval_one(vv[it].x, rep, lane8);
                o.y = eval_one(vv[it].y, rep, lane8);
                o.z = eval_one(vv[it].z, rep, lane8);
                o.w = eval_one(vv[it].w, rep, lane8);
                y4[i] = o;
            }
        }
    }

    // scalar tail (n % 4 != 0) — block 0 only
    if (blockIdx.x == 0) {
        int j = n4 * 4 + tid;
        if (j < n) y[j] = eval_one(x[j], rep, lane8);
    }
}

extern "C" void kernel_launch(void* const* d_in, const int* in_sizes, int n_in,
                              void* d_out, int out_size) {
    const float* x         = (const float*)d_in[0];
    // d_in[1] = grid (uniform; values implied by construction)
    const float* c0        = (const float*)d_in[2];
    const float* raw_delta = (const float*)d_in[3];
    float* y = (float*)d_out;

    int n  = in_sizes[0];
    int n4 = n / 4;

    int per_block = THREADS * ITEMS;
    int blocks = (n4 + per_block - 1) / per_block;
    if (blocks == 0) blocks = 1;

    // primary: tiny prep
    prep_kernel<<<1, 32>>>(c0, raw_delta);

    // secondary: eval with programmatic stream serialization (PDL overlap)
    cudaLaunchConfig_t cfg = {};
    cfg.gridDim  = dim3((unsigned)blocks, 1, 1);
    cfg.blockDim = dim3(THREADS, 1, 1);
    cfg.dynamicSmemBytes = 0;
    cfg.stream = 0;   // same (legacy default) stream the harness captures
    cudaLaunchAttribute attrs[1];
    attrs[0].id = cudaLaunchAttributeProgrammaticStreamSerialization;
    attrs[0].val.programmaticStreamSerializationAllowed = 1;
    cfg.attrs = attrs;
    cfg.numAttrs = 1;
    cudaLaunchKernelEx(&cfg, spline_eval_kernel, x, y, n4, n);
}